// round 14
// baseline (speedup 1.0000x reference)
#include <cuda_runtime.h>
#include <cuda_bf16.h>
#include <math.h>
#include <stdint.h>

// Problem constants
#define NB   96   // nodes
#define DD   64   // feature dim
#define BS   16   // batch
#define TT   13   // sequence length (12 steps)
#define SZ   (BS * NB * DD)

#define STU  36   // shared row stride in u32 (= 72 bf16): conflict-free ldmatrix
#define KBT  384  // kB threads (12 warps)

// kB dynamic smem layout (bytes)
#define OFF_THI  0        // u32[192*36]  27648
#define OFF_TLO  27648    // u32[192*36]  27648
#define OFF_WHI  55296    // u32[64*36]    9216
#define OFF_WLO  64512    // u32[64*36]    9216
#define OFF_ADJ  73728    // float[2*96]    768
#define OFF_B2   74496    // float[64]      256
#define OFF_RED  74752    // float[2*2*3*32] 1536
#define KB_SMEM  76288

// Scratch state (allocation-free rule: __device__ globals)
__device__ float g_hidden[SZ];
__device__ float g_S[SZ];
__device__ float g_R[SZ];
__device__ float g_agg[SZ];
__device__ float g_Xall[NB * 3 * DD];   // per-skill input projections (xr|xi|xn)

// W2^T split into bf16 hi/lo, packed 2 k's per u32: layout [d][kp]; 16B-aligned for cp.async
__device__ __align__(16) uint32_t g_w2t_hi[2048];
__device__ __align__(16) uint32_t g_w2t_lo[2048];

__device__ __forceinline__ float tanh_fast(float x) {
    float y;
    asm("tanh.approx.f32 %0, %1;" : "=f"(y) : "f"(x));
    return y;
}
__device__ __forceinline__ float sigmoid_acc(float x) {
    return 1.0f / (1.0f + expf(-x));
}
__device__ __forceinline__ uint32_t smem_u32(const void* p) {
    uint32_t a;
    asm("{ .reg .u64 t; cvta.to.shared.u64 t, %1; cvt.u32.u64 %0, t; }" : "=r"(a) : "l"(p));
    return a;
}
__device__ __forceinline__ void cp_async16(uint32_t smem_addr, const void* gptr) {
    asm volatile("cp.async.ca.shared.global [%0], [%1], 16;"
        :: "r"(smem_addr), "l"(gptr) : "memory");
}
__device__ __forceinline__ void ldm_x4(uint32_t a[4], uint32_t addr) {
    asm volatile("ldmatrix.sync.aligned.m8n8.x4.shared.b16 {%0,%1,%2,%3}, [%4];"
        : "=r"(a[0]), "=r"(a[1]), "=r"(a[2]), "=r"(a[3]) : "r"(addr));
}
__device__ __forceinline__ void mma_bf16(float c[4], const uint32_t a[4],
                                         uint32_t b0, uint32_t b1) {
    asm volatile("mma.sync.aligned.m16n8k16.row.col.f32.bf16.bf16.f32 "
        "{%0,%1,%2,%3}, {%4,%5,%6,%7}, {%8,%9}, {%0,%1,%2,%3};"
        : "+f"(c[0]), "+f"(c[1]), "+f"(c[2]), "+f"(c[3])
        : "r"(a[0]), "r"(a[1]), "r"(a[2]), "r"(a[3]), "r"(b0), "r"(b1));
}
__device__ __forceinline__ uint32_t pack_bf16x2(float lo_val, float hi_val) {
    __nv_bfloat16 l = __float2bfloat16(lo_val);
    __nv_bfloat16 h = __float2bfloat16(hi_val);
    return ((uint32_t)__bfloat16_as_ushort(h) << 16) | __bfloat16_as_ushort(l);
}

// ---------------------------------------------------------------------------
__global__ void kInit() {
    int idx = blockIdx.x * blockDim.x + threadIdx.x;
    if (idx < SZ) {
        g_hidden[idx] = 0.0f;
        g_S[idx] = 0.0f;
        g_R[idx] = 0.0f;
    }
}

// Prep (once): Wt[d][k] = W2[k][d], bf16 hi/lo split, 2 k's packed per u32.
__global__ void kPrep(const float* __restrict__ W2) {
    int tid = threadIdx.x;
    for (int idx = tid; idx < 2048; idx += 256) {
        int d  = idx >> 5;
        int kp = idx & 31;
        float w0 = W2[(2 * kp)     * DD + d];
        float w1 = W2[(2 * kp + 1) * DD + d];
        __nv_bfloat16 h0 = __float2bfloat16(w0);
        __nv_bfloat16 h1 = __float2bfloat16(w1);
        g_w2t_hi[idx] = ((uint32_t)__bfloat16_as_ushort(h1) << 16) | __bfloat16_as_ushort(h0);
        g_w2t_lo[idx] = pack_bf16x2(w0 - __bfloat162float(h0), w1 - __bfloat162float(h1));
    }
}

// Prep (once): per-skill input projections Xall[s][g*64+d] = b_g[d] + emb[s]@W_g
__global__ void kPrepX(const float* __restrict__ emb,
                       const float* __restrict__ W_ir, const float* __restrict__ b_ir,
                       const float* __restrict__ W_ii, const float* __restrict__ b_ii,
                       const float* __restrict__ W_in, const float* __restrict__ b_in) {
    __shared__ float sE[DD];
    int s = blockIdx.x;
    int tid = threadIdx.x;          // 192 threads
    if (tid < DD) sE[tid] = emb[s * DD + tid];
    __syncthreads();
    int g = tid >> 6, d = tid & 63;
    const float* W  = (g == 0) ? W_ir : (g == 1) ? W_ii : W_in;
    const float* bb = (g == 0) ? b_ir : (g == 1) ? b_ii : b_in;
    float a = bb[d];
#pragma unroll 8
    for (int k = 0; k < DD; k++) a = fmaf(sE[k], W[k * DD + d], a);
    g_Xall[s * (3 * DD) + g * DD + d] = a;
}

// ---------------------------------------------------------------------------
// Kernel B: 768 CTAs, 384 thr / 12 warps. CTA = (b, i0) with 2 receiver rows,
// 192 flat m-rows. Warp = (pair p 0..5 of 32 rows, d-half h 0..1).
// Warp builds ITS OWN 16 T-rows (rv in registers, coalesced S LDG, STS),
// fully before the single cp.async-wait barrier. Then MMA (2mt x 4nt),
// epilogue, one more barrier, 128-thread combine. 2 block barriers total.
// ---------------------------------------------------------------------------
__global__ void __launch_bounds__(KBT, 2) kB(
    const float* __restrict__ adj,     // (1,16,96,96)
    const float* __restrict__ bm1,     // (64)
    const float* __restrict__ b2)      // (64)
{
    extern __shared__ __align__(16) char smem[];
    uint32_t* sThi = reinterpret_cast<uint32_t*>(smem + OFF_THI);   // 192 rows
    uint32_t* sTlo = reinterpret_cast<uint32_t*>(smem + OFF_TLO);
    float*    sAdj = reinterpret_cast<float*>(smem + OFF_ADJ);      // 2 rows
    float*    sB2  = reinterpret_cast<float*>(smem + OFF_B2);
    float*    sRed = reinterpret_cast<float*>(smem + OFF_RED);      // [ii][h][pj][32]

    const int bx   = blockIdx.x;
    const int b    = bx / (NB / 2);
    const int i0   = (bx % (NB / 2)) * 2;
    const int tid  = threadIdx.x;
    const int wid  = tid >> 5;
    const int lane = tid & 31;

    const int p  = wid >> 1;          // 0..5 row-pair
    const int h  = wid & 1;           // d-half
    const int ii = p / 3;             // receiver index (0/1)
    const int pj = p % 3;             // pair within receiver

    const uint32_t tThi = smem_u32(sThi);
    const uint32_t tTlo = smem_u32(sTlo);
    const uint32_t tWhi = smem_u32(smem + OFF_WHI);
    const uint32_t tWlo = smem_u32(smem + OFF_WLO);

    // ---- 1. cp.async W staging ----
    for (int idx = tid; idx < 512; idx += KBT) {
        int d   = idx >> 3;
        int kp4 = (idx & 7) * 4;
        uint32_t soff = (uint32_t)(d * STU + kp4) * 4;
        cp_async16(tWhi + soff, &g_w2t_hi[d * 32 + kp4]);
        cp_async16(tWlo + soff, &g_w2t_lo[d * 32 + kp4]);
    }
    asm volatile("cp.async.commit_group;" ::: "memory");

    // ---- 2. stage adj rows + b2 (plain stores; visible after barrier 1) ----
    if (tid < 2 * NB)
        sAdj[tid] = adj[(b * NB + i0) * NB + tid];
    if (tid < DD) sB2[tid] = b2[tid];

    // ---- 3. receiver vector in registers: lane k holds rv[2k], rv[2k+1] ----
    float2 rvp;
    {
        const float2 r2 = *reinterpret_cast<const float2*>(
            &g_R[(b * NB + i0 + ii) * DD + lane * 2]);
        const float2 bb = *reinterpret_cast<const float2*>(&bm1[lane * 2]);
        rvp.x = r2.x + bb.x;
        rvp.y = r2.y + bb.y;
    }

    // ---- 4. build own 16 T-rows: row = p*32 + h*16 + it, kp = lane ----
    {
        const int rbase = p * 32 + h * 16;
        const int jbase = rbase - ii * NB;                 // S row index
        const float* Sb = &g_S[b * NB * DD];
#pragma unroll
        for (int it = 0; it < 16; it++) {
            const int row = rbase + it;
            const int j   = jbase + it;
            float2 s = *reinterpret_cast<const float2*>(&Sb[j * DD + lane * 2]);
            float t0 = tanh_fast(s.x + rvp.x);
            float t1 = tanh_fast(s.y + rvp.y);
            __nv_bfloat16 h0 = __float2bfloat16(t0);
            __nv_bfloat16 h1 = __float2bfloat16(t1);
            sThi[row * STU + lane] =
                ((uint32_t)__bfloat16_as_ushort(h1) << 16) | __bfloat16_as_ushort(h0);
            sTlo[row * STU + lane] =
                pack_bf16x2(t0 - __bfloat162float(h0), t1 - __bfloat162float(h1));
        }
    }

    // ---- 5. W arrived + T/adj visible ----
    asm volatile("cp.async.wait_group 0;" ::: "memory");
    __syncthreads();

    // ---- 6. HMMA: warp covers rows [p*32, p*32+32), d [h*32, h*32+32) ----
    const int a_joff = (lane & 7) + ((lane & 8) ? 8 : 0);
    const int a_koff = (lane & 16) ? 8 : 0;
    const int b_row  = (lane & 7) + ((lane & 16) ? 8 : 0);   // d-row within 16
    const int b_k8   = (lane & 8) ? 8 : 0;
    const int g4 = lane >> 2;
    const int c4 = lane & 3;

    float c[2][4][4];
#pragma unroll
    for (int mt = 0; mt < 2; mt++)
#pragma unroll
        for (int nt = 0; nt < 4; nt++)
#pragma unroll
            for (int r = 0; r < 4; r++) c[mt][nt][r] = 0.0f;

#pragma unroll
    for (int ks = 0; ks < 4; ks++) {
        const int k0 = ks * 16;
        // B (W) fragments: 2 x ldm_x4 per image, each covering 2 n-tiles
        uint32_t bhi[2][4], blo[2][4];
#pragma unroll
        for (int q = 0; q < 2; q++) {
            uint32_t boff = ((h * 32 + q * 16 + b_row) * STU + ((k0 + b_k8) >> 1)) * 4;
            ldm_x4(bhi[q], tWhi + boff);
            ldm_x4(blo[q], tWlo + boff);
        }
#pragma unroll
        for (int mt = 0; mt < 2; mt++) {
            const int rm = p * 32 + mt * 16;
            uint32_t aoff = ((rm + a_joff) * STU + ((k0 + a_koff) >> 1)) * 4;
            uint32_t ahi[4], alo[4];
            ldm_x4(ahi, tThi + aoff);
            ldm_x4(alo, tTlo + aoff);
#pragma unroll
            for (int q = 0; q < 2; q++) {
#pragma unroll
                for (int s = 0; s < 2; s++) {
                    const int nt = q * 2 + s;
                    mma_bf16(c[mt][nt], ahi, bhi[q][2 * s], bhi[q][2 * s + 1]);
                    mma_bf16(c[mt][nt], alo, bhi[q][2 * s], bhi[q][2 * s + 1]);
                    mma_bf16(c[mt][nt], ahi, blo[q][2 * s], blo[q][2 * s + 1]);
                }
            }
        }
    }

    // ---- 7. epilogue: tanh + adj-weighted j-reduction ----
    float accd[4][2];
#pragma unroll
    for (int nt = 0; nt < 4; nt++) { accd[nt][0] = 0.f; accd[nt][1] = 0.f; }
    float b2v[4][2];
#pragma unroll
    for (int nt = 0; nt < 4; nt++) {
        b2v[nt][0] = sB2[h * 32 + nt * 8 + 2 * c4];
        b2v[nt][1] = sB2[h * 32 + nt * 8 + 2 * c4 + 1];
    }
    const float* adjRow = &sAdj[ii * NB];
#pragma unroll
    for (int mt = 0; mt < 2; mt++) {
        const int jloc = pj * 32 + mt * 16;
        float aj0 = adjRow[jloc + g4];
        float aj1 = adjRow[jloc + 8 + g4];
#pragma unroll
        for (int nt = 0; nt < 4; nt++) {
            accd[nt][0] = fmaf(aj0, tanh_fast(c[mt][nt][0] + b2v[nt][0]), accd[nt][0]);
            accd[nt][1] = fmaf(aj0, tanh_fast(c[mt][nt][1] + b2v[nt][1]), accd[nt][1]);
            accd[nt][0] = fmaf(aj1, tanh_fast(c[mt][nt][2] + b2v[nt][0]), accd[nt][0]);
            accd[nt][1] = fmaf(aj1, tanh_fast(c[mt][nt][3] + b2v[nt][1]), accd[nt][1]);
        }
    }
#pragma unroll
    for (int off = 4; off <= 16; off <<= 1) {
#pragma unroll
        for (int nt = 0; nt < 4; nt++) {
            accd[nt][0] += __shfl_xor_sync(0xffffffffu, accd[nt][0], off);
            accd[nt][1] += __shfl_xor_sync(0xffffffffu, accd[nt][1], off);
        }
    }
    if (lane < 4) {
        float* red = &sRed[(((ii * 2 + h) * 3) + pj) * 32];
#pragma unroll
        for (int nt = 0; nt < 4; nt++) {
            red[nt * 8 + 2 * lane]     = accd[nt][0];
            red[nt * 8 + 2 * lane + 1] = accd[nt][1];
        }
    }
    __syncthreads();

    // ---- 8. combine 3 pair-partials per (ii, d) ----
    if (tid < 2 * DD) {
        const int iw = tid >> 6;
        const int d  = tid & 63;
        const int hh = d >> 5;
        const int dl = d & 31;
        const float* base = &sRed[((iw * 2 + hh) * 3) * 32];
        g_agg[(b * NB + i0 + iw) * DD + d] =
            (base[dl] + base[32 + dl] + base[64 + dl]) * (1.0f / 96.0f);
    }
}

// ---------------------------------------------------------------------------
// Kernel C (light, split-K): 384 blocks, 4 rows each; thread = (d, kc).
// ---------------------------------------------------------------------------
#define RPB 4    // rows per block (== number of kc groups)

__global__ void __launch_bounds__(256) kC(
    int t,
    const int*   __restrict__ skill_seq,  // (16,13)
    const float* __restrict__ W_hr, const float* __restrict__ W_hi,
    const float* __restrict__ W_hh,
    const float* __restrict__ W_o1, const float* __restrict__ b_o1,
    const float* __restrict__ W_o2, const float* __restrict__ b_o2,
    const float* __restrict__ W_o3, const float* __restrict__ b_o3,
    const float* __restrict__ W_msg1,     // (128,64)
    float* __restrict__ out)              // (1,16,12,96,64)
{
    __shared__ float sA[RPB * DD];
    __shared__ float sHN[RPB * DD];
    __shared__ float sP[RPB * DD];
    __shared__ float sP2[RPB * DD];
    __shared__ float sPart[4][RPB][3][DD];   // kc, row, gate, d  = 12 KB

    const int bx  = blockIdx.x;
    const int b   = bx / 24;
    const int n0  = (bx % 24) * RPB;
    const int tid = threadIdx.x;
    const int d   = tid & 63;
    const int kc  = tid >> 6;             // 0..3
    const int k0  = kc * 16;

    const int base = (b * NB + n0) * DD;
    for (int idx = tid; idx < RPB * DD; idx += 256)
        sA[idx] = g_agg[base + idx];
    __syncthreads();

    // ---- Stage A: GRU gates (split-K partials) ----
    {
        float pr[RPB], pi[RPB], ph[RPB];
#pragma unroll
        for (int r = 0; r < RPB; r++) { pr[r] = 0.f; pi[r] = 0.f; ph[r] = 0.f; }
#pragma unroll
        for (int kk = 0; kk < 16; kk++) {
            int k = k0 + kk;
            float whr = W_hr[k * DD + d];
            float whi = W_hi[k * DD + d];
            float whh = W_hh[k * DD + d];
#pragma unroll
            for (int r = 0; r < RPB; r++) {
                float av = sA[r * DD + k];
                pr[r] = fmaf(av, whr, pr[r]);
                pi[r] = fmaf(av, whi, pi[r]);
                ph[r] = fmaf(av, whh, ph[r]);
            }
        }
#pragma unroll
        for (int r = 0; r < RPB; r++) {
            sPart[kc][r][0][d] = pr[r];
            sPart[kc][r][1][d] = pi[r];
            sPart[kc][r][2][d] = ph[r];
        }
    }
    __syncthreads();

    // combine + GRU update: thread (d, r=kc)
    {
        const int r = kc;
        float ahr = sPart[0][r][0][d] + sPart[1][r][0][d] + sPart[2][r][0][d] + sPart[3][r][0][d];
        float ahi = sPart[0][r][1][d] + sPart[1][r][1][d] + sPart[2][r][1][d] + sPart[3][r][1][d];
        float ahh = sPart[0][r][2][d] + sPart[1][r][2][d] + sPart[2][r][2][d] + sPart[3][r][2][d];
        int skill = skill_seq[b * TT + t];
        const float* X = &g_Xall[skill * (3 * DD)];
        float rr = sigmoid_acc(X[d] + ahr);
        float ii = sigmoid_acc(X[DD + d] + ahi);
        float nn = tanhf(X[2 * DD + d] + rr * ahh);
        float h  = g_hidden[base + r * DD + d];
        float hn = (1.0f - ii) * nn + ii * h;
        g_hidden[base + r * DD + d] = hn;
        sHN[r * DD + d] = hn;
    }
    __syncthreads();

    // ---- Stage B: pred layer1 + Snext + R (split-K) ----
    {
        float p1[RPB], pS[RPB], pR[RPB];
#pragma unroll
        for (int r = 0; r < RPB; r++) { p1[r] = 0.f; pS[r] = 0.f; pR[r] = 0.f; }
#pragma unroll
        for (int kk = 0; kk < 16; kk++) {
            int k = k0 + kk;
            float w1 = W_o1[k * DD + d];
            float wS = W_msg1[k * DD + d];
            float wR = W_msg1[(DD + k) * DD + d];
#pragma unroll
            for (int r = 0; r < RPB; r++) {
                float hv = sHN[r * DD + k];
                p1[r] = fmaf(hv, w1, p1[r]);
                pS[r] = fmaf(hv, wS, pS[r]);
                pR[r] = fmaf(hv, wR, pR[r]);
            }
        }
#pragma unroll
        for (int r = 0; r < RPB; r++) {
            sPart[kc][r][0][d] = p1[r];
            sPart[kc][r][1][d] = pS[r];
            sPart[kc][r][2][d] = pR[r];
        }
    }
    __syncthreads();
    {
        const int r = kc;
        float a1 = sPart[0][r][0][d] + sPart[1][r][0][d] + sPart[2][r][0][d] + sPart[3][r][0][d];
        float aS = sPart[0][r][1][d] + sPart[1][r][1][d] + sPart[2][r][1][d] + sPart[3][r][1][d];
        float aR = sPart[0][r][2][d] + sPart[1][r][2][d] + sPart[2][r][2][d] + sPart[3][r][2][d];
        sP[r * DD + d] = fmaxf(a1 + b_o1[d], 0.0f);
        g_S[base + r * DD + d] = aS;
        g_R[base + r * DD + d] = aR;
    }
    __syncthreads();

    // ---- Stage C: pred layer2 (split-K) ----
    {
        float p2[RPB];
#pragma unroll
        for (int r = 0; r < RPB; r++) p2[r] = 0.f;
#pragma unroll
        for (int kk = 0; kk < 16; kk++) {
            int k = k0 + kk;
            float w2 = W_o2[k * DD + d];
#pragma unroll
            for (int r = 0; r < RPB; r++)
                p2[r] = fmaf(sP[r * DD + k], w2, p2[r]);
        }
#pragma unroll
        for (int r = 0; r < RPB; r++)
            sPart[kc][r][0][d] = p2[r];
    }
    __syncthreads();
    {
        const int r = kc;
        float a2 = sPart[0][r][0][d] + sPart[1][r][0][d] + sPart[2][r][0][d] + sPart[3][r][0][d];
        sP2[r * DD + d] = fmaxf(a2 + b_o2[d], 0.0f);
    }
    __syncthreads();

    // ---- Stage D: pred layer3 -> out (split-K) ----
    {
        float p3[RPB];
#pragma unroll
        for (int r = 0; r < RPB; r++) p3[r] = 0.f;
#pragma unroll
        for (int kk = 0; kk < 16; kk++) {
            int k = k0 + kk;
            float w3 = W_o3[k * DD + d];
#pragma unroll
            for (int r = 0; r < RPB; r++)
                p3[r] = fmaf(sP2[r * DD + k], w3, p3[r]);
        }
#pragma unroll
        for (int r = 0; r < RPB; r++)
            sPart[kc][r][0][d] = p3[r];
    }
    __syncthreads();
    {
        const int r = kc;
        float a3 = sPart[0][r][0][d] + sPart[1][r][0][d] + sPart[2][r][0][d] + sPart[3][r][0][d];
        out[(((size_t)b * 12 + t) * NB + (n0 + r)) * DD + d] = a3 + b_o3[d];
    }
}

// ---------------------------------------------------------------------------
extern "C" void kernel_launch(void* const* d_in, const int* in_sizes, int n_in,
                              void* d_out, int out_size) {
    const int*   skill_seq = (const int*)  d_in[0];
    const float* adj       = (const float*)d_in[1];
    const float* node_emb  = (const float*)d_in[2];
    const float* W_msg1    = (const float*)d_in[3];
    const float* b_msg1    = (const float*)d_in[4];
    const float* W_msg2    = (const float*)d_in[5];
    const float* b_msg2    = (const float*)d_in[6];
    const float* W_hr      = (const float*)d_in[7];
    const float* W_hi      = (const float*)d_in[8];
    const float* W_hh      = (const float*)d_in[9];
    const float* W_ir      = (const float*)d_in[10];
    const float* b_ir      = (const float*)d_in[11];
    const float* W_ii      = (const float*)d_in[12];
    const float* b_ii      = (const float*)d_in[13];
    const float* W_in      = (const float*)d_in[14];
    const float* b_in      = (const float*)d_in[15];
    const float* W_o1      = (const float*)d_in[16];
    const float* b_o1      = (const float*)d_in[17];
    const float* W_o2      = (const float*)d_in[18];
    const float* b_o2      = (const float*)d_in[19];
    const float* W_o3      = (const float*)d_in[20];
    const float* b_o3      = (const float*)d_in[21];
    float* out = (float*)d_out;

    cudaFuncSetAttribute(kB, cudaFuncAttributeMaxDynamicSharedMemorySize, KB_SMEM);

    kInit<<<(SZ + 255) / 256, 256>>>();
    kPrep<<<1, 256>>>(W_msg2);
    kPrepX<<<NB, 192>>>(node_emb, W_ir, b_ir, W_ii, b_ii, W_in, b_in);

    for (int t = 0; t < TT - 1; t++) {
        kB<<<BS * (NB / 2), KBT, KB_SMEM>>>(adj, b_msg1, b_msg2);
        kC<<<BS * 24, 256>>>(t, skill_seq,
                             W_hr, W_hi, W_hh,
                             W_o1, b_o1, W_o2, b_o2, W_o3, b_o3,
                             W_msg1, out);
    }
}

// round 15
// speedup vs baseline: 1.3085x; 1.3085x over previous
#include <cuda_runtime.h>
#include <cuda_bf16.h>
#include <math.h>
#include <stdint.h>

// Problem constants
#define NB   96   // nodes
#define DD   64   // feature dim
#define BS   16   // batch
#define TT   13   // sequence length (12 steps)
#define SZ   (BS * NB * DD)

#define STU  36   // shared row stride in u32 (= 72 bf16): conflict-free ldmatrix
#define KBT  384  // kB threads (12 warps)

// Scratch state (allocation-free rule: __device__ globals)
__device__ float g_hidden[SZ];
__device__ float g_S[SZ];
__device__ float g_R[SZ];
__device__ float g_agg[SZ];
__device__ float g_Xall[NB * 3 * DD];   // per-skill input projections (xr|xi|xn)

// W2^T bf16, packed 2 k's per u32: layout [d][kp]; 16B-aligned for cp.async
__device__ __align__(16) uint32_t g_w2t[2048];

__device__ __forceinline__ float tanh_fast(float x) {
    float y;
    asm("tanh.approx.f32 %0, %1;" : "=f"(y) : "f"(x));
    return y;
}
__device__ __forceinline__ float sigmoid_acc(float x) {
    return 1.0f / (1.0f + expf(-x));
}
__device__ __forceinline__ uint32_t smem_u32(const void* p) {
    uint32_t a;
    asm("{ .reg .u64 t; cvta.to.shared.u64 t, %1; cvt.u32.u64 %0, t; }" : "=r"(a) : "l"(p));
    return a;
}
__device__ __forceinline__ void cp_async16(uint32_t smem_addr, const void* gptr) {
    asm volatile("cp.async.ca.shared.global [%0], [%1], 16;"
        :: "r"(smem_addr), "l"(gptr) : "memory");
}
__device__ __forceinline__ void ldm_x4(uint32_t a[4], uint32_t addr) {
    asm volatile("ldmatrix.sync.aligned.m8n8.x4.shared.b16 {%0,%1,%2,%3}, [%4];"
        : "=r"(a[0]), "=r"(a[1]), "=r"(a[2]), "=r"(a[3]) : "r"(addr));
}
__device__ __forceinline__ void mma_bf16(float c[4], const uint32_t a[4],
                                         uint32_t b0, uint32_t b1) {
    asm volatile("mma.sync.aligned.m16n8k16.row.col.f32.bf16.bf16.f32 "
        "{%0,%1,%2,%3}, {%4,%5,%6,%7}, {%8,%9}, {%0,%1,%2,%3};"
        : "+f"(c[0]), "+f"(c[1]), "+f"(c[2]), "+f"(c[3])
        : "r"(a[0]), "r"(a[1]), "r"(a[2]), "r"(a[3]), "r"(b0), "r"(b1));
}
__device__ __forceinline__ uint32_t pack2_bf16(float v0, float v1) {
    __nv_bfloat16 h0 = __float2bfloat16(v0);
    __nv_bfloat16 h1 = __float2bfloat16(v1);
    return ((uint32_t)__bfloat16_as_ushort(h1) << 16) | __bfloat16_as_ushort(h0);
}

// ---------------------------------------------------------------------------
__global__ void kInit() {
    int idx = blockIdx.x * blockDim.x + threadIdx.x;
    if (idx < SZ) {
        g_hidden[idx] = 0.0f;
        g_S[idx] = 0.0f;
        g_R[idx] = 0.0f;
    }
}

// Prep (once): Wt[d][k] = W2[k][d], bf16, 2 k's packed per u32.
__global__ void kPrep(const float* __restrict__ W2) {
    int tid = threadIdx.x;
    for (int idx = tid; idx < 2048; idx += 256) {
        int d  = idx >> 5;
        int kp = idx & 31;
        g_w2t[idx] = pack2_bf16(W2[(2 * kp) * DD + d], W2[(2 * kp + 1) * DD + d]);
    }
}

// Prep (once): per-skill input projections Xall[s][g*64+d] = b_g[d] + emb[s]@W_g
__global__ void kPrepX(const float* __restrict__ emb,
                       const float* __restrict__ W_ir, const float* __restrict__ b_ir,
                       const float* __restrict__ W_ii, const float* __restrict__ b_ii,
                       const float* __restrict__ W_in, const float* __restrict__ b_in) {
    __shared__ float sE[DD];
    int s = blockIdx.x;
    int tid = threadIdx.x;          // 192 threads
    if (tid < DD) sE[tid] = emb[s * DD + tid];
    __syncthreads();
    int g = tid >> 6, d = tid & 63;
    const float* W  = (g == 0) ? W_ir : (g == 1) ? W_ii : W_in;
    const float* bb = (g == 0) ? b_ir : (g == 1) ? b_ii : b_in;
    float a = bb[d];
#pragma unroll 8
    for (int k = 0; k < DD; k++) a = fmaf(sE[k], W[k * DD + d], a);
    g_Xall[s * (3 * DD) + g * DD + d] = a;
}

// ---------------------------------------------------------------------------
// Kernel B: 768 CTAs, 384 thr / 12 warps. CTA = (b, i0) with 2 receiver rows,
// 192 flat m-rows. SINGLE-PASS bf16 (accuracy headroom spent for speed).
// Warp = (pair p 0..5 of 32 rows, d-half h 0..1); builds its own 16 T-rows,
// then MMA (2mt x 4nt, 32 HMMA), epilogue, combine. 2 block barriers.
// ---------------------------------------------------------------------------
__global__ void __launch_bounds__(KBT, 3) kB(
    const float* __restrict__ adj,     // (1,16,96,96)
    const float* __restrict__ bm1,     // (64)
    const float* __restrict__ b2)      // (64)
{
    __shared__ __align__(16) uint32_t sT[192 * STU];   // 27648 B
    __shared__ __align__(16) uint32_t sW[DD * STU];    //  9216 B
    __shared__ float sAdj[2 * NB];
    __shared__ float sB2[DD];
    __shared__ float sRed[2 * 2 * 3 * 32];             // [ii][h][pj][32]

    const int bx   = blockIdx.x;
    const int b    = bx / (NB / 2);
    const int i0   = (bx % (NB / 2)) * 2;
    const int tid  = threadIdx.x;
    const int wid  = tid >> 5;
    const int lane = tid & 31;

    const int p  = wid >> 1;          // 0..5 row-pair
    const int h  = wid & 1;           // d-half
    const int ii = p / 3;             // receiver index (0/1)
    const int pj = p % 3;             // pair within receiver

    const uint32_t tT = smem_u32(sT);
    const uint32_t tW = smem_u32(sW);

    // ---- 1. cp.async W staging (512 x 16B chunks) ----
    for (int idx = tid; idx < 512; idx += KBT) {
        int d   = idx >> 3;
        int kp4 = (idx & 7) * 4;
        cp_async16(tW + (uint32_t)(d * STU + kp4) * 4, &g_w2t[d * 32 + kp4]);
    }
    asm volatile("cp.async.commit_group;" ::: "memory");

    // ---- 2. stage adj rows + b2 ----
    if (tid < 2 * NB)
        sAdj[tid] = adj[(b * NB + i0) * NB + tid];
    if (tid < DD) sB2[tid] = b2[tid];

    // ---- 3. receiver vector in registers: lane k holds rv[2k], rv[2k+1] ----
    float2 rvp;
    {
        const float2 r2 = *reinterpret_cast<const float2*>(
            &g_R[(b * NB + i0 + ii) * DD + lane * 2]);
        const float2 bb = *reinterpret_cast<const float2*>(&bm1[lane * 2]);
        rvp.x = r2.x + bb.x;
        rvp.y = r2.y + bb.y;
    }

    // ---- 4. build own 16 T-rows (bf16, single image) ----
    {
        const int rbase = p * 32 + h * 16;
        const int jbase = rbase - ii * NB;
        const float* Sb = &g_S[b * NB * DD];
#pragma unroll
        for (int it = 0; it < 16; it++) {
            const int row = rbase + it;
            float2 s = *reinterpret_cast<const float2*>(&Sb[(jbase + it) * DD + lane * 2]);
            sT[row * STU + lane] =
                pack2_bf16(tanh_fast(s.x + rvp.x), tanh_fast(s.y + rvp.y));
        }
    }

    // ---- 5. W arrived + T/adj visible ----
    asm volatile("cp.async.wait_group 0;" ::: "memory");
    __syncthreads();

    // ---- 6. HMMA: warp covers rows [p*32, p*32+32), d [h*32, h*32+32) ----
    const int a_joff = (lane & 7) + ((lane & 8) ? 8 : 0);
    const int a_koff = (lane & 16) ? 8 : 0;
    const int b_row  = (lane & 7) + ((lane & 16) ? 8 : 0);
    const int b_k8   = (lane & 8) ? 8 : 0;
    const int g4 = lane >> 2;
    const int c4 = lane & 3;

    float c[2][4][4];
#pragma unroll
    for (int mt = 0; mt < 2; mt++)
#pragma unroll
        for (int nt = 0; nt < 4; nt++)
#pragma unroll
            for (int r = 0; r < 4; r++) c[mt][nt][r] = 0.0f;

#pragma unroll
    for (int ks = 0; ks < 4; ks++) {
        const int k0 = ks * 16;
        uint32_t bw[2][4];
#pragma unroll
        for (int q = 0; q < 2; q++) {
            uint32_t boff = ((h * 32 + q * 16 + b_row) * STU + ((k0 + b_k8) >> 1)) * 4;
            ldm_x4(bw[q], tW + boff);
        }
#pragma unroll
        for (int mt = 0; mt < 2; mt++) {
            const int rm = p * 32 + mt * 16;
            uint32_t aoff = ((rm + a_joff) * STU + ((k0 + a_koff) >> 1)) * 4;
            uint32_t aw[4];
            ldm_x4(aw, tT + aoff);
#pragma unroll
            for (int q = 0; q < 2; q++) {
#pragma unroll
                for (int s = 0; s < 2; s++)
                    mma_bf16(c[mt][q * 2 + s], aw, bw[q][2 * s], bw[q][2 * s + 1]);
            }
        }
    }

    // ---- 7. epilogue: tanh + adj-weighted j-reduction ----
    float accd[4][2];
#pragma unroll
    for (int nt = 0; nt < 4; nt++) { accd[nt][0] = 0.f; accd[nt][1] = 0.f; }
    float b2v[4][2];
#pragma unroll
    for (int nt = 0; nt < 4; nt++) {
        b2v[nt][0] = sB2[h * 32 + nt * 8 + 2 * c4];
        b2v[nt][1] = sB2[h * 32 + nt * 8 + 2 * c4 + 1];
    }
    const float* adjRow = &sAdj[ii * NB];
#pragma unroll
    for (int mt = 0; mt < 2; mt++) {
        const int jloc = pj * 32 + mt * 16;
        float aj0 = adjRow[jloc + g4];
        float aj1 = adjRow[jloc + 8 + g4];
#pragma unroll
        for (int nt = 0; nt < 4; nt++) {
            accd[nt][0] = fmaf(aj0, tanh_fast(c[mt][nt][0] + b2v[nt][0]), accd[nt][0]);
            accd[nt][1] = fmaf(aj0, tanh_fast(c[mt][nt][1] + b2v[nt][1]), accd[nt][1]);
            accd[nt][0] = fmaf(aj1, tanh_fast(c[mt][nt][2] + b2v[nt][0]), accd[nt][0]);
            accd[nt][1] = fmaf(aj1, tanh_fast(c[mt][nt][3] + b2v[nt][1]), accd[nt][1]);
        }
    }
#pragma unroll
    for (int off = 4; off <= 16; off <<= 1) {
#pragma unroll
        for (int nt = 0; nt < 4; nt++) {
            accd[nt][0] += __shfl_xor_sync(0xffffffffu, accd[nt][0], off);
            accd[nt][1] += __shfl_xor_sync(0xffffffffu, accd[nt][1], off);
        }
    }
    if (lane < 4) {
        float* red = &sRed[(((ii * 2 + h) * 3) + pj) * 32];
#pragma unroll
        for (int nt = 0; nt < 4; nt++) {
            red[nt * 8 + 2 * lane]     = accd[nt][0];
            red[nt * 8 + 2 * lane + 1] = accd[nt][1];
        }
    }
    __syncthreads();

    // ---- 8. combine 3 pair-partials per (ii, d) ----
    if (tid < 2 * DD) {
        const int iw = tid >> 6;
        const int d  = tid & 63;
        const int hh = d >> 5;
        const int dl = d & 31;
        const float* base = &sRed[((iw * 2 + hh) * 3) * 32];
        g_agg[(b * NB + i0 + iw) * DD + d] =
            (base[dl] + base[32 + dl] + base[64 + dl]) * (1.0f / 96.0f);
    }
}

// ---------------------------------------------------------------------------
// Kernel C (light, split-K): 384 blocks, 4 rows each; thread = (d, kc).
// ---------------------------------------------------------------------------
#define RPB 4    // rows per block (== number of kc groups)

__global__ void __launch_bounds__(256) kC(
    int t,
    const int*   __restrict__ skill_seq,  // (16,13)
    const float* __restrict__ W_hr, const float* __restrict__ W_hi,
    const float* __restrict__ W_hh,
    const float* __restrict__ W_o1, const float* __restrict__ b_o1,
    const float* __restrict__ W_o2, const float* __restrict__ b_o2,
    const float* __restrict__ W_o3, const float* __restrict__ b_o3,
    const float* __restrict__ W_msg1,     // (128,64)
    float* __restrict__ out)              // (1,16,12,96,64)
{
    __shared__ float sA[RPB * DD];
    __shared__ float sHN[RPB * DD];
    __shared__ float sP[RPB * DD];
    __shared__ float sP2[RPB * DD];
    __shared__ float sPart[4][RPB][3][DD];   // kc, row, gate, d  = 12 KB

    const int bx  = blockIdx.x;
    const int b   = bx / 24;
    const int n0  = (bx % 24) * RPB;
    const int tid = threadIdx.x;
    const int d   = tid & 63;
    const int kc  = tid >> 6;             // 0..3
    const int k0  = kc * 16;

    const int base = (b * NB + n0) * DD;
    for (int idx = tid; idx < RPB * DD; idx += 256)
        sA[idx] = g_agg[base + idx];
    __syncthreads();

    // ---- Stage A: GRU gates (split-K partials) ----
    {
        float pr[RPB], pi[RPB], ph[RPB];
#pragma unroll
        for (int r = 0; r < RPB; r++) { pr[r] = 0.f; pi[r] = 0.f; ph[r] = 0.f; }
#pragma unroll
        for (int kk = 0; kk < 16; kk++) {
            int k = k0 + kk;
            float whr = W_hr[k * DD + d];
            float whi = W_hi[k * DD + d];
            float whh = W_hh[k * DD + d];
#pragma unroll
            for (int r = 0; r < RPB; r++) {
                float av = sA[r * DD + k];
                pr[r] = fmaf(av, whr, pr[r]);
                pi[r] = fmaf(av, whi, pi[r]);
                ph[r] = fmaf(av, whh, ph[r]);
            }
        }
#pragma unroll
        for (int r = 0; r < RPB; r++) {
            sPart[kc][r][0][d] = pr[r];
            sPart[kc][r][1][d] = pi[r];
            sPart[kc][r][2][d] = ph[r];
        }
    }
    __syncthreads();

    // combine + GRU update: thread (d, r=kc)
    {
        const int r = kc;
        float ahr = sPart[0][r][0][d] + sPart[1][r][0][d] + sPart[2][r][0][d] + sPart[3][r][0][d];
        float ahi = sPart[0][r][1][d] + sPart[1][r][1][d] + sPart[2][r][1][d] + sPart[3][r][1][d];
        float ahh = sPart[0][r][2][d] + sPart[1][r][2][d] + sPart[2][r][2][d] + sPart[3][r][2][d];
        int skill = skill_seq[b * TT + t];
        const float* X = &g_Xall[skill * (3 * DD)];
        float rr = sigmoid_acc(X[d] + ahr);
        float ii = sigmoid_acc(X[DD + d] + ahi);
        float nn = tanhf(X[2 * DD + d] + rr * ahh);
        float h  = g_hidden[base + r * DD + d];
        float hn = (1.0f - ii) * nn + ii * h;
        g_hidden[base + r * DD + d] = hn;
        sHN[r * DD + d] = hn;
    }
    __syncthreads();

    // ---- Stage B: pred layer1 + Snext + R (split-K) ----
    {
        float p1[RPB], pS[RPB], pR[RPB];
#pragma unroll
        for (int r = 0; r < RPB; r++) { p1[r] = 0.f; pS[r] = 0.f; pR[r] = 0.f; }
#pragma unroll
        for (int kk = 0; kk < 16; kk++) {
            int k = k0 + kk;
            float w1 = W_o1[k * DD + d];
            float wS = W_msg1[k * DD + d];
            float wR = W_msg1[(DD + k) * DD + d];
#pragma unroll
            for (int r = 0; r < RPB; r++) {
                float hv = sHN[r * DD + k];
                p1[r] = fmaf(hv, w1, p1[r]);
                pS[r] = fmaf(hv, wS, pS[r]);
                pR[r] = fmaf(hv, wR, pR[r]);
            }
        }
#pragma unroll
        for (int r = 0; r < RPB; r++) {
            sPart[kc][r][0][d] = p1[r];
            sPart[kc][r][1][d] = pS[r];
            sPart[kc][r][2][d] = pR[r];
        }
    }
    __syncthreads();
    {
        const int r = kc;
        float a1 = sPart[0][r][0][d] + sPart[1][r][0][d] + sPart[2][r][0][d] + sPart[3][r][0][d];
        float aS = sPart[0][r][1][d] + sPart[1][r][1][d] + sPart[2][r][1][d] + sPart[3][r][1][d];
        float aR = sPart[0][r][2][d] + sPart[1][r][2][d] + sPart[2][r][2][d] + sPart[3][r][2][d];
        sP[r * DD + d] = fmaxf(a1 + b_o1[d], 0.0f);
        g_S[base + r * DD + d] = aS;
        g_R[base + r * DD + d] = aR;
    }
    __syncthreads();

    // ---- Stage C: pred layer2 (split-K) ----
    {
        float p2[RPB];
#pragma unroll
        for (int r = 0; r < RPB; r++) p2[r] = 0.f;
#pragma unroll
        for (int kk = 0; kk < 16; kk++) {
            int k = k0 + kk;
            float w2 = W_o2[k * DD + d];
#pragma unroll
            for (int r = 0; r < RPB; r++)
                p2[r] = fmaf(sP[r * DD + k], w2, p2[r]);
        }
#pragma unroll
        for (int r = 0; r < RPB; r++)
            sPart[kc][r][0][d] = p2[r];
    }
    __syncthreads();
    {
        const int r = kc;
        float a2 = sPart[0][r][0][d] + sPart[1][r][0][d] + sPart[2][r][0][d] + sPart[3][r][0][d];
        sP2[r * DD + d] = fmaxf(a2 + b_o2[d], 0.0f);
    }
    __syncthreads();

    // ---- Stage D: pred layer3 -> out (split-K) ----
    {
        float p3[RPB];
#pragma unroll
        for (int r = 0; r < RPB; r++) p3[r] = 0.f;
#pragma unroll
        for (int kk = 0; kk < 16; kk++) {
            int k = k0 + kk;
            float w3 = W_o3[k * DD + d];
#pragma unroll
            for (int r = 0; r < RPB; r++)
                p3[r] = fmaf(sP2[r * DD + k], w3, p3[r]);
        }
#pragma unroll
        for (int r = 0; r < RPB; r++)
            sPart[kc][r][0][d] = p3[r];
    }
    __syncthreads();
    {
        const int r = kc;
        float a3 = sPart[0][r][0][d] + sPart[1][r][0][d] + sPart[2][r][0][d] + sPart[3][r][0][d];
        out[(((size_t)b * 12 + t) * NB + (n0 + r)) * DD + d] = a3 + b_o3[d];
    }
}

// ---------------------------------------------------------------------------
extern "C" void kernel_launch(void* const* d_in, const int* in_sizes, int n_in,
                              void* d_out, int out_size) {
    const int*   skill_seq = (const int*)  d_in[0];
    const float* adj       = (const float*)d_in[1];
    const float* node_emb  = (const float*)d_in[2];
    const float* W_msg1    = (const float*)d_in[3];
    const float* b_msg1    = (const float*)d_in[4];
    const float* W_msg2    = (const float*)d_in[5];
    const float* b_msg2    = (const float*)d_in[6];
    const float* W_hr      = (const float*)d_in[7];
    const float* W_hi      = (const float*)d_in[8];
    const float* W_hh      = (const float*)d_in[9];
    const float* W_ir      = (const float*)d_in[10];
    const float* b_ir      = (const float*)d_in[11];
    const float* W_ii      = (const float*)d_in[12];
    const float* b_ii      = (const float*)d_in[13];
    const float* W_in      = (const float*)d_in[14];
    const float* b_in      = (const float*)d_in[15];
    const float* W_o1      = (const float*)d_in[16];
    const float* b_o1      = (const float*)d_in[17];
    const float* W_o2      = (const float*)d_in[18];
    const float* b_o2      = (const float*)d_in[19];
    const float* W_o3      = (const float*)d_in[20];
    const float* b_o3      = (const float*)d_in[21];
    float* out = (float*)d_out;

    kInit<<<(SZ + 255) / 256, 256>>>();
    kPrep<<<1, 256>>>(W_msg2);
    kPrepX<<<NB, 192>>>(node_emb, W_ir, b_ir, W_ii, b_ii, W_in, b_in);

    for (int t = 0; t < TT - 1; t++) {
        kB<<<BS * (NB / 2), KBT>>>(adj, b_msg1, b_msg2);
        kC<<<BS * 24, 256>>>(t, skill_seq,
                             W_hr, W_hi, W_hh,
                             W_o1, b_o1, W_o2, b_o2, W_o3, b_o3,
                             W_msg1, out);
    }
}

// round 16
// speedup vs baseline: 1.3674x; 1.0450x over previous
#include <cuda_runtime.h>
#include <cuda_bf16.h>
#include <math.h>
#include <stdint.h>

// Problem constants
#define NB   96   // nodes
#define DD   64   // feature dim
#define BS   16   // batch
#define TT   13   // sequence length (12 steps)
#define SZ   (BS * NB * DD)

#define STU  36   // shared row stride in u32 (= 72 bf16): conflict-free ldmatrix
#define KBT  384  // kB threads (12 warps)

// Scratch state (allocation-free rule: __device__ globals)
__device__ float g_hidden[SZ];
__device__ float g_S[SZ];
__device__ float g_R[SZ];
__device__ float g_agg[SZ];
__device__ float g_Xall[NB * 3 * DD];   // per-skill input projections (xr|xi|xn)

// W2^T bf16, packed 2 k's per u32: layout [d][kp]; 16B-aligned for cp.async
__device__ __align__(16) uint32_t g_w2t[2048];

__device__ __forceinline__ float tanh_fast(float x) {
    float y;
    asm("tanh.approx.f32 %0, %1;" : "=f"(y) : "f"(x));
    return y;
}
__device__ __forceinline__ float sigmoid_acc(float x) {
    return 1.0f / (1.0f + expf(-x));
}
__device__ __forceinline__ uint32_t smem_u32(const void* p) {
    uint32_t a;
    asm("{ .reg .u64 t; cvta.to.shared.u64 t, %1; cvt.u32.u64 %0, t; }" : "=r"(a) : "l"(p));
    return a;
}
__device__ __forceinline__ void cp_async16(uint32_t smem_addr, const void* gptr) {
    asm volatile("cp.async.ca.shared.global [%0], [%1], 16;"
        :: "r"(smem_addr), "l"(gptr) : "memory");
}
__device__ __forceinline__ void ldm_x4(uint32_t a[4], uint32_t addr) {
    asm volatile("ldmatrix.sync.aligned.m8n8.x4.shared.b16 {%0,%1,%2,%3}, [%4];"
        : "=r"(a[0]), "=r"(a[1]), "=r"(a[2]), "=r"(a[3]) : "r"(addr));
}
__device__ __forceinline__ void mma_bf16(float c[4], const uint32_t a[4],
                                         uint32_t b0, uint32_t b1) {
    asm volatile("mma.sync.aligned.m16n8k16.row.col.f32.bf16.bf16.f32 "
        "{%0,%1,%2,%3}, {%4,%5,%6,%7}, {%8,%9}, {%0,%1,%2,%3};"
        : "+f"(c[0]), "+f"(c[1]), "+f"(c[2]), "+f"(c[3])
        : "r"(a[0]), "r"(a[1]), "r"(a[2]), "r"(a[3]), "r"(b0), "r"(b1));
}
__device__ __forceinline__ uint32_t pack2_bf16(float v0, float v1) {
    __nv_bfloat16 h0 = __float2bfloat16(v0);
    __nv_bfloat16 h1 = __float2bfloat16(v1);
    return ((uint32_t)__bfloat16_as_ushort(h1) << 16) | __bfloat16_as_ushort(h0);
}
// one-instruction pack: low = lo_val, high = hi_val
__device__ __forceinline__ uint32_t cvt_bf16x2(float hi_val, float lo_val) {
    uint32_t r;
    asm("cvt.rn.bf16x2.f32 %0, %1, %2;" : "=r"(r) : "f"(hi_val), "f"(lo_val));
    return r;
}

// ---------------------------------------------------------------------------
__global__ void kInit() {
    int idx = blockIdx.x * blockDim.x + threadIdx.x;
    if (idx < SZ) {
        g_hidden[idx] = 0.0f;
        g_S[idx] = 0.0f;
        g_R[idx] = 0.0f;
    }
}

// Prep (once): Wt[d][k] = W2[k][d], bf16, 2 k's packed per u32.
__global__ void kPrep(const float* __restrict__ W2) {
    int tid = threadIdx.x;
    for (int idx = tid; idx < 2048; idx += 256) {
        int d  = idx >> 5;
        int kp = idx & 31;
        g_w2t[idx] = pack2_bf16(W2[(2 * kp) * DD + d], W2[(2 * kp + 1) * DD + d]);
    }
}

// Prep (once): per-skill input projections Xall[s][g*64+d] = b_g[d] + emb[s]@W_g
__global__ void kPrepX(const float* __restrict__ emb,
                       const float* __restrict__ W_ir, const float* __restrict__ b_ir,
                       const float* __restrict__ W_ii, const float* __restrict__ b_ii,
                       const float* __restrict__ W_in, const float* __restrict__ b_in) {
    __shared__ float sE[DD];
    int s = blockIdx.x;
    int tid = threadIdx.x;          // 192 threads
    if (tid < DD) sE[tid] = emb[s * DD + tid];
    __syncthreads();
    int g = tid >> 6, d = tid & 63;
    const float* W  = (g == 0) ? W_ir : (g == 1) ? W_ii : W_in;
    const float* bb = (g == 0) ? b_ir : (g == 1) ? b_ii : b_in;
    float a = bb[d];
#pragma unroll 8
    for (int k = 0; k < DD; k++) a = fmaf(sE[k], W[k * DD + d], a);
    g_Xall[s * (3 * DD) + g * DD + d] = a;
}

// ---------------------------------------------------------------------------
// Kernel B: 768 CTAs, 384 thr / 12 warps. CTA = (b, i0) with 2 receiver rows,
// 192 flat m-rows. Single-pass bf16. Warp = (pair p 0..5, d-half h 0..1).
// T-build: float4 path — thread handles 4 k's of one row; warp does 2 rows
// per iteration (8 iters), cvt.rn.bf16x2 single-instruction packing, STS.64.
// ---------------------------------------------------------------------------
__global__ void __launch_bounds__(KBT, 3) kB(
    const float* __restrict__ adj,     // (1,16,96,96)
    const float* __restrict__ bm1,     // (64)
    const float* __restrict__ b2)      // (64)
{
    __shared__ __align__(16) uint32_t sT[192 * STU];   // 27648 B
    __shared__ __align__(16) uint32_t sW[DD * STU];    //  9216 B
    __shared__ float sAdj[2 * NB];
    __shared__ float sB2[DD];
    __shared__ float sRed[2 * 2 * 3 * 32];             // [ii][h][pj][32]

    const int bx   = blockIdx.x;
    const int b    = bx / (NB / 2);
    const int i0   = (bx % (NB / 2)) * 2;
    const int tid  = threadIdx.x;
    const int wid  = tid >> 5;
    const int lane = tid & 31;

    const int p  = wid >> 1;          // 0..5 row-pair
    const int h  = wid & 1;           // d-half
    const int ii = p / 3;             // receiver index (0/1)
    const int pj = p % 3;             // pair within receiver

    const uint32_t tT = smem_u32(sT);
    const uint32_t tW = smem_u32(sW);

    // ---- 1. cp.async W staging (512 x 16B chunks) ----
    for (int idx = tid; idx < 512; idx += KBT) {
        int d   = idx >> 3;
        int kp4 = (idx & 7) * 4;
        cp_async16(tW + (uint32_t)(d * STU + kp4) * 4, &g_w2t[d * 32 + kp4]);
    }
    asm volatile("cp.async.commit_group;" ::: "memory");

    // ---- 2. stage adj rows + b2 ----
    if (tid < 2 * NB)
        sAdj[tid] = adj[(b * NB + i0) * NB + tid];
    if (tid < DD) sB2[tid] = b2[tid];

    // ---- 3. receiver vector (4 k's) in registers ----
    const int rh = lane >> 4;         // row parity within warp-iteration
    const int kq = lane & 15;         // k-quad index
    float4 rv4;
    {
        const float4 r4 = *reinterpret_cast<const float4*>(
            &g_R[(b * NB + i0 + ii) * DD + kq * 4]);
        const float4 b4 = *reinterpret_cast<const float4*>(&bm1[kq * 4]);
        rv4 = make_float4(r4.x + b4.x, r4.y + b4.y, r4.z + b4.z, r4.w + b4.w);
    }

    // ---- 4. build own 16 T-rows: 8 iters, 2 rows/iter, float4 per thread ----
    {
        const int rbase = p * 32 + h * 16;
        const int jbase = rbase - ii * NB;
        const float* Sb = &g_S[b * NB * DD];
#pragma unroll
        for (int it = 0; it < 8; it++) {
            const int row = rbase + it * 2 + rh;
            const int j   = jbase + it * 2 + rh;
            float4 s = *reinterpret_cast<const float4*>(&Sb[j * DD + kq * 4]);
            float t0 = tanh_fast(s.x + rv4.x);
            float t1 = tanh_fast(s.y + rv4.y);
            float t2 = tanh_fast(s.z + rv4.z);
            float t3 = tanh_fast(s.w + rv4.w);
            uint2 u;
            u.x = cvt_bf16x2(t1, t0);
            u.y = cvt_bf16x2(t3, t2);
            *reinterpret_cast<uint2*>(&sT[row * STU + kq * 2]) = u;
        }
    }

    // ---- 5. W arrived + T/adj visible ----
    asm volatile("cp.async.wait_group 0;" ::: "memory");
    __syncthreads();

    // ---- 6. HMMA: warp covers rows [p*32, p*32+32), d [h*32, h*32+32) ----
    const int a_joff = (lane & 7) + ((lane & 8) ? 8 : 0);
    const int a_koff = (lane & 16) ? 8 : 0;
    const int b_row  = (lane & 7) + ((lane & 16) ? 8 : 0);
    const int b_k8   = (lane & 8) ? 8 : 0;
    const int g4 = lane >> 2;
    const int c4 = lane & 3;

    float c[2][4][4];
#pragma unroll
    for (int mt = 0; mt < 2; mt++)
#pragma unroll
        for (int nt = 0; nt < 4; nt++)
#pragma unroll
            for (int r = 0; r < 4; r++) c[mt][nt][r] = 0.0f;

#pragma unroll
    for (int ks = 0; ks < 4; ks++) {
        const int k0 = ks * 16;
        uint32_t bw[2][4];
#pragma unroll
        for (int q = 0; q < 2; q++) {
            uint32_t boff = ((h * 32 + q * 16 + b_row) * STU + ((k0 + b_k8) >> 1)) * 4;
            ldm_x4(bw[q], tW + boff);
        }
#pragma unroll
        for (int mt = 0; mt < 2; mt++) {
            const int rm = p * 32 + mt * 16;
            uint32_t aoff = ((rm + a_joff) * STU + ((k0 + a_koff) >> 1)) * 4;
            uint32_t aw[4];
            ldm_x4(aw, tT + aoff);
#pragma unroll
            for (int q = 0; q < 2; q++) {
#pragma unroll
                for (int s = 0; s < 2; s++)
                    mma_bf16(c[mt][q * 2 + s], aw, bw[q][2 * s], bw[q][2 * s + 1]);
            }
        }
    }

    // ---- 7. epilogue: tanh + adj-weighted j-reduction ----
    float accd[4][2];
#pragma unroll
    for (int nt = 0; nt < 4; nt++) { accd[nt][0] = 0.f; accd[nt][1] = 0.f; }
    float b2v[4][2];
#pragma unroll
    for (int nt = 0; nt < 4; nt++) {
        b2v[nt][0] = sB2[h * 32 + nt * 8 + 2 * c4];
        b2v[nt][1] = sB2[h * 32 + nt * 8 + 2 * c4 + 1];
    }
    const float* adjRow = &sAdj[ii * NB];
#pragma unroll
    for (int mt = 0; mt < 2; mt++) {
        const int jloc = pj * 32 + mt * 16;
        float aj0 = adjRow[jloc + g4];
        float aj1 = adjRow[jloc + 8 + g4];
#pragma unroll
        for (int nt = 0; nt < 4; nt++) {
            accd[nt][0] = fmaf(aj0, tanh_fast(c[mt][nt][0] + b2v[nt][0]), accd[nt][0]);
            accd[nt][1] = fmaf(aj0, tanh_fast(c[mt][nt][1] + b2v[nt][1]), accd[nt][1]);
            accd[nt][0] = fmaf(aj1, tanh_fast(c[mt][nt][2] + b2v[nt][0]), accd[nt][0]);
            accd[nt][1] = fmaf(aj1, tanh_fast(c[mt][nt][3] + b2v[nt][1]), accd[nt][1]);
        }
    }
#pragma unroll
    for (int off = 4; off <= 16; off <<= 1) {
#pragma unroll
        for (int nt = 0; nt < 4; nt++) {
            accd[nt][0] += __shfl_xor_sync(0xffffffffu, accd[nt][0], off);
            accd[nt][1] += __shfl_xor_sync(0xffffffffu, accd[nt][1], off);
        }
    }
    if (lane < 4) {
        float* red = &sRed[(((ii * 2 + h) * 3) + pj) * 32];
#pragma unroll
        for (int nt = 0; nt < 4; nt++) {
            red[nt * 8 + 2 * lane]     = accd[nt][0];
            red[nt * 8 + 2 * lane + 1] = accd[nt][1];
        }
    }
    __syncthreads();

    // ---- 8. combine 3 pair-partials per (ii, d) ----
    if (tid < 2 * DD) {
        const int iw = tid >> 6;
        const int d  = tid & 63;
        const int hh = d >> 5;
        const int dl = d & 31;
        const float* base = &sRed[((iw * 2 + hh) * 3) * 32];
        g_agg[(b * NB + i0 + iw) * DD + d] =
            (base[dl] + base[32 + dl] + base[64 + dl]) * (1.0f / 96.0f);
    }
}

// ---------------------------------------------------------------------------
// Kernel C (light, split-K): 384 blocks, 4 rows each; thread = (d, kc).
// ---------------------------------------------------------------------------
#define RPB 4    // rows per block (== number of kc groups)

__global__ void __launch_bounds__(256) kC(
    int t,
    const int*   __restrict__ skill_seq,  // (16,13)
    const float* __restrict__ W_hr, const float* __restrict__ W_hi,
    const float* __restrict__ W_hh,
    const float* __restrict__ W_o1, const float* __restrict__ b_o1,
    const float* __restrict__ W_o2, const float* __restrict__ b_o2,
    const float* __restrict__ W_o3, const float* __restrict__ b_o3,
    const float* __restrict__ W_msg1,     // (128,64)
    float* __restrict__ out)              // (1,16,12,96,64)
{
    __shared__ float sA[RPB * DD];
    __shared__ float sHN[RPB * DD];
    __shared__ float sP[RPB * DD];
    __shared__ float sP2[RPB * DD];
    __shared__ float sPart[4][RPB][3][DD];   // kc, row, gate, d  = 12 KB

    const int bx  = blockIdx.x;
    const int b   = bx / 24;
    const int n0  = (bx % 24) * RPB;
    const int tid = threadIdx.x;
    const int d   = tid & 63;
    const int kc  = tid >> 6;             // 0..3
    const int k0  = kc * 16;

    const int base = (b * NB + n0) * DD;
    for (int idx = tid; idx < RPB * DD; idx += 256)
        sA[idx] = g_agg[base + idx];
    __syncthreads();

    // ---- Stage A: GRU gates (split-K partials) ----
    {
        float pr[RPB], pi[RPB], ph[RPB];
#pragma unroll
        for (int r = 0; r < RPB; r++) { pr[r] = 0.f; pi[r] = 0.f; ph[r] = 0.f; }
#pragma unroll
        for (int kk = 0; kk < 16; kk++) {
            int k = k0 + kk;
            float whr = W_hr[k * DD + d];
            float whi = W_hi[k * DD + d];
            float whh = W_hh[k * DD + d];
#pragma unroll
            for (int r = 0; r < RPB; r++) {
                float av = sA[r * DD + k];
                pr[r] = fmaf(av, whr, pr[r]);
                pi[r] = fmaf(av, whi, pi[r]);
                ph[r] = fmaf(av, whh, ph[r]);
            }
        }
#pragma unroll
        for (int r = 0; r < RPB; r++) {
            sPart[kc][r][0][d] = pr[r];
            sPart[kc][r][1][d] = pi[r];
            sPart[kc][r][2][d] = ph[r];
        }
    }
    __syncthreads();

    // combine + GRU update: thread (d, r=kc)
    {
        const int r = kc;
        float ahr = sPart[0][r][0][d] + sPart[1][r][0][d] + sPart[2][r][0][d] + sPart[3][r][0][d];
        float ahi = sPart[0][r][1][d] + sPart[1][r][1][d] + sPart[2][r][1][d] + sPart[3][r][1][d];
        float ahh = sPart[0][r][2][d] + sPart[1][r][2][d] + sPart[2][r][2][d] + sPart[3][r][2][d];
        int skill = skill_seq[b * TT + t];
        const float* X = &g_Xall[skill * (3 * DD)];
        float rr = sigmoid_acc(X[d] + ahr);
        float ii = sigmoid_acc(X[DD + d] + ahi);
        float nn = tanhf(X[2 * DD + d] + rr * ahh);
        float h  = g_hidden[base + r * DD + d];
        float hn = (1.0f - ii) * nn + ii * h;
        g_hidden[base + r * DD + d] = hn;
        sHN[r * DD + d] = hn;
    }
    __syncthreads();

    // ---- Stage B: pred layer1 + Snext + R (split-K) ----
    {
        float p1[RPB], pS[RPB], pR[RPB];
#pragma unroll
        for (int r = 0; r < RPB; r++) { p1[r] = 0.f; pS[r] = 0.f; pR[r] = 0.f; }
#pragma unroll
        for (int kk = 0; kk < 16; kk++) {
            int k = k0 + kk;
            float w1 = W_o1[k * DD + d];
            float wS = W_msg1[k * DD + d];
            float wR = W_msg1[(DD + k) * DD + d];
#pragma unroll
            for (int r = 0; r < RPB; r++) {
                float hv = sHN[r * DD + k];
                p1[r] = fmaf(hv, w1, p1[r]);
                pS[r] = fmaf(hv, wS, pS[r]);
                pR[r] = fmaf(hv, wR, pR[r]);
            }
        }
#pragma unroll
        for (int r = 0; r < RPB; r++) {
            sPart[kc][r][0][d] = p1[r];
            sPart[kc][r][1][d] = pS[r];
            sPart[kc][r][2][d] = pR[r];
        }
    }
    __syncthreads();
    {
        const int r = kc;
        float a1 = sPart[0][r][0][d] + sPart[1][r][0][d] + sPart[2][r][0][d] + sPart[3][r][0][d];
        float aS = sPart[0][r][1][d] + sPart[1][r][1][d] + sPart[2][r][1][d] + sPart[3][r][1][d];
        float aR = sPart[0][r][2][d] + sPart[1][r][2][d] + sPart[2][r][2][d] + sPart[3][r][2][d];
        sP[r * DD + d] = fmaxf(a1 + b_o1[d], 0.0f);
        g_S[base + r * DD + d] = aS;
        g_R[base + r * DD + d] = aR;
    }
    __syncthreads();

    // ---- Stage C: pred layer2 (split-K) ----
    {
        float p2[RPB];
#pragma unroll
        for (int r = 0; r < RPB; r++) p2[r] = 0.f;
#pragma unroll
        for (int kk = 0; kk < 16; kk++) {
            int k = k0 + kk;
            float w2 = W_o2[k * DD + d];
#pragma unroll
            for (int r = 0; r < RPB; r++)
                p2[r] = fmaf(sP[r * DD + k], w2, p2[r]);
        }
#pragma unroll
        for (int r = 0; r < RPB; r++)
            sPart[kc][r][0][d] = p2[r];
    }
    __syncthreads();
    {
        const int r = kc;
        float a2 = sPart[0][r][0][d] + sPart[1][r][0][d] + sPart[2][r][0][d] + sPart[3][r][0][d];
        sP2[r * DD + d] = fmaxf(a2 + b_o2[d], 0.0f);
    }
    __syncthreads();

    // ---- Stage D: pred layer3 -> out (split-K) ----
    {
        float p3[RPB];
#pragma unroll
        for (int r = 0; r < RPB; r++) p3[r] = 0.f;
#pragma unroll
        for (int kk = 0; kk < 16; kk++) {
            int k = k0 + kk;
            float w3 = W_o3[k * DD + d];
#pragma unroll
            for (int r = 0; r < RPB; r++)
                p3[r] = fmaf(sP2[r * DD + k], w3, p3[r]);
        }
#pragma unroll
        for (int r = 0; r < RPB; r++)
            sPart[kc][r][0][d] = p3[r];
    }
    __syncthreads();
    {
        const int r = kc;
        float a3 = sPart[0][r][0][d] + sPart[1][r][0][d] + sPart[2][r][0][d] + sPart[3][r][0][d];
        out[(((size_t)b * 12 + t) * NB + (n0 + r)) * DD + d] = a3 + b_o3[d];
    }
}

// ---------------------------------------------------------------------------
extern "C" void kernel_launch(void* const* d_in, const int* in_sizes, int n_in,
                              void* d_out, int out_size) {
    const int*   skill_seq = (const int*)  d_in[0];
    const float* adj       = (const float*)d_in[1];
    const float* node_emb  = (const float*)d_in[2];
    const float* W_msg1    = (const float*)d_in[3];
    const float* b_msg1    = (const float*)d_in[4];
    const float* W_msg2    = (const float*)d_in[5];
    const float* b_msg2    = (const float*)d_in[6];
    const float* W_hr      = (const float*)d_in[7];
    const float* W_hi      = (const float*)d_in[8];
    const float* W_hh      = (const float*)d_in[9];
    const float* W_ir      = (const float*)d_in[10];
    const float* b_ir      = (const float*)d_in[11];
    const float* W_ii      = (const float*)d_in[12];
    const float* b_ii      = (const float*)d_in[13];
    const float* W_in      = (const float*)d_in[14];
    const float* b_in      = (const float*)d_in[15];
    const float* W_o1      = (const float*)d_in[16];
    const float* b_o1      = (const float*)d_in[17];
    const float* W_o2      = (const float*)d_in[18];
    const float* b_o2      = (const float*)d_in[19];
    const float* W_o3      = (const float*)d_in[20];
    const float* b_o3      = (const float*)d_in[21];
    float* out = (float*)d_out;

    kInit<<<(SZ + 255) / 256, 256>>>();
    kPrep<<<1, 256>>>(W_msg2);
    kPrepX<<<NB, 192>>>(node_emb, W_ir, b_ir, W_ii, b_ii, W_in, b_in);

    for (int t = 0; t < TT - 1; t++) {
        kB<<<BS * (NB / 2), KBT>>>(adj, b_msg1, b_msg2);
        kC<<<BS * 24, 256>>>(t, skill_seq,
                             W_hr, W_hi, W_hh,
                             W_o1, b_o1, W_o2, b_o2, W_o3, b_o3,
                             W_msg1, out);
    }
}